// round 16
// baseline (speedup 1.0000x reference)
#include <cuda_runtime.h>
#include <cuda_bf16.h>
#include <cuda_fp16.h>
#include <cstdint>
#include <math.h>

// ===========================================================================
// Net_6983616823390 — binarized MLP (sm_103)
//  L1 : fp16 HMMA K=3072 + exact fp32 fixup of |pre|<α·TAU (TAU=0.05)
//  L2-4: bf16 HMMA {0,1}x{-1,0,+1} exact, K=2016 (bit-exact trim)
//  Scale finalizes INLINED into consumer epilogues (bit-identical 256-thread
//  replication of the 512-thread tree) — 6 launches removed.
//  L5 : fp32 SIMT
// ===========================================================================

#define B_ROWS 8192
#define HDIM   2000
#define HPAD   2048
#define DIN    3072
#define KTRIM  2016

#define RED_BLOCKS 512
#define RED_THREADS 256
#define GPARTS 1024
#define APAD 40
#define CAPN (1u << 21)
#define TAU  0.05f

#define INV_NW1 (1.0 / 6144000.0)    // 1/(2000*3072)
#define INV_NW  (1.0 / 4000000.0)    // 1/(2000*2000)
#define INV_H   (1.0 / 16384000.0)   // 1/(8192*2000)

__device__ double d_partials[8][GPARTS];
__device__ double d_corr;
__device__ unsigned d_flagcnt;
__device__ uint32_t d_rec_mn[CAPN];
__device__ float    d_rec_h[CAPN];

__device__ __align__(16) __half g_xh [(size_t)B_ROWS * DIN];
__device__ __align__(16) __half g_w1h[(size_t)HPAD * DIN];
__device__ __align__(16) __nv_bfloat16 g_sw2[(size_t)HPAD * HPAD];
__device__ __align__(16) __nv_bfloat16 g_sw3[(size_t)HPAD * HPAD];
__device__ __align__(16) __nv_bfloat16 g_sw4[(size_t)HPAD * HPAD];
__device__ __align__(16) __nv_bfloat16 g_stepA[(size_t)B_ROWS * HPAD];
__device__ __align__(16) __nv_bfloat16 g_stepB[(size_t)B_ROWS * HPAD];
__device__ __align__(16) float g_h4[(size_t)B_ROWS * HDIM];

__device__ __forceinline__ uint32_t smem_u32(const void* p) {
    uint32_t a;
    asm("{ .reg .u64 t; cvta.to.shared.u64 t, %1; cvt.u32.u64 %0, t; }" : "=r"(a) : "l"(p));
    return a;
}
__device__ __forceinline__ void ldm_x4(uint32_t* r, uint32_t addr) {
    asm volatile("ldmatrix.sync.aligned.m8n8.x4.shared.b16 {%0,%1,%2,%3}, [%4];"
        : "=r"(r[0]), "=r"(r[1]), "=r"(r[2]), "=r"(r[3]) : "r"(addr));
}
__device__ __forceinline__ void mma_bf16(float* c, const uint32_t* a,
                                         uint32_t b0, uint32_t b1) {
    asm volatile(
        "mma.sync.aligned.m16n8k16.row.col.f32.bf16.bf16.f32 "
        "{%0,%1,%2,%3}, {%4,%5,%6,%7}, {%8,%9}, {%0,%1,%2,%3};"
        : "+f"(c[0]), "+f"(c[1]), "+f"(c[2]), "+f"(c[3])
        : "r"(a[0]), "r"(a[1]), "r"(a[2]), "r"(a[3]), "r"(b0), "r"(b1));
}
__device__ __forceinline__ void mma_f16(float* c, const uint32_t* a,
                                        uint32_t b0, uint32_t b1) {
    asm volatile(
        "mma.sync.aligned.m16n8k16.row.col.f32.f16.f16.f32 "
        "{%0,%1,%2,%3}, {%4,%5,%6,%7}, {%8,%9}, {%0,%1,%2,%3};"
        : "+f"(c[0]), "+f"(c[1]), "+f"(c[2]), "+f"(c[3])
        : "r"(a[0]), "r"(a[1]), "r"(a[2]), "r"(a[3]), "r"(b0), "r"(b1));
}

// ---------------------------------------------------------------------------
// Inline scale reductions — 256-thread, BIT-IDENTICAL to the former
// 512-thread reduce_finalize trees (leaf = first combine level).
// Requires all 256 threads; sm = 256-double scratch.
// ---------------------------------------------------------------------------
__device__ __forceinline__ float scale_from_512(const double* __restrict__ p,
                                                double invn, double* sm, int tid) {
    sm[tid] = p[tid] + p[tid + 256];
    __syncthreads();
    for (int o = 128; o > 0; o >>= 1) {
        if (tid < o) sm[tid] += sm[tid + o];
        __syncthreads();
    }
    double s = sm[0];
    __syncthreads();
    return (float)(s * invn);
}
__device__ __forceinline__ float scale_from_1024(const double* __restrict__ p,
                                                 double invn, double corr,
                                                 double* sm, int tid) {
    sm[tid] = (p[tid] + p[tid + 512]) + (p[tid + 256] + p[tid + 768]);
    __syncthreads();
    for (int o = 128; o > 0; o >>= 1) {
        if (tid < o) sm[tid] += sm[tid + o];
        __syncthreads();
    }
    double s = sm[0] + corr;
    __syncthreads();
    return (float)(s * invn);
}

// ===========================================================================
// Deterministic |.| partial reduction (slots 0..3, 512 blocks)
// ===========================================================================
__global__ void __launch_bounds__(RED_THREADS)
reduce_abs_partial(const float* __restrict__ src, long n, int slot) {
    double s = 0.0;
    long stride = (long)gridDim.x * blockDim.x;
    for (long i = (long)blockIdx.x * blockDim.x + threadIdx.x; i < n; i += stride)
        s += (double)fabsf(src[i]);
    __shared__ double sm[RED_THREADS];
    sm[threadIdx.x] = s; __syncthreads();
    for (int o = RED_THREADS / 2; o > 0; o >>= 1) {
        if (threadIdx.x < o) sm[threadIdx.x] += sm[threadIdx.x + o];
        __syncthreads();
    }
    if (threadIdx.x == 0) d_partials[slot][blockIdx.x] = sm[0];
}

// ===========================================================================
// Conversions / init
// ===========================================================================
__global__ void k_init() {
    d_flagcnt = 0u;
    d_corr = 0.0;
}
__global__ void __launch_bounds__(256)
k_cvt_x(const float* __restrict__ x) {
    long gid = (long)blockIdx.x * blockDim.x + threadIdx.x;
    long n8 = (long)B_ROWS * DIN / 8;
    if (gid >= n8) return;
    const float4 v0 = *(const float4*)&x[gid * 8];
    const float4 v1 = *(const float4*)&x[gid * 8 + 4];
    __half2 h0 = __floats2half2_rn(v0.x, v0.y);
    __half2 h1 = __floats2half2_rn(v0.z, v0.w);
    __half2 h2 = __floats2half2_rn(v1.x, v1.y);
    __half2 h3 = __floats2half2_rn(v1.z, v1.w);
    uint4 o;
    o.x = *(uint32_t*)&h0; o.y = *(uint32_t*)&h1;
    o.z = *(uint32_t*)&h2; o.w = *(uint32_t*)&h3;
    *(uint4*)&g_xh[gid * 8] = o;
}
__global__ void __launch_bounds__(256)
k_sign_w1h(const float* __restrict__ W1) {
    long gid = (long)blockIdx.x * blockDim.x + threadIdx.x;
    long n2 = (long)HPAD * DIN / 2;
    if (gid >= n2) return;
    int r = (int)(gid / (DIN / 2));
    int c = (int)(gid % (DIN / 2)) * 2;
    uint32_t w = 0;
    if (r < HDIM) {
        float a = W1[(size_t)r * DIN + c], b = W1[(size_t)r * DIN + c + 1];
        uint32_t lo = (a > 0.f) ? 0x3C00u : ((a < 0.f) ? 0xBC00u : 0u);
        uint32_t hi = (b > 0.f) ? 0x3C00u : ((b < 0.f) ? 0xBC00u : 0u);
        w = lo | (hi << 16);
    }
    *(uint32_t*)&g_w1h[(size_t)r * DIN + c] = w;
}
__device__ __forceinline__ uint32_t sgn_pair_bf(float a, float b) {
    uint32_t lo = (a > 0.f) ? 0x3F80u : ((a < 0.f) ? 0xBF80u : 0u);
    uint32_t hi = (b > 0.f) ? 0x3F80u : ((b < 0.f) ? 0xBF80u : 0u);
    return lo | (hi << 16);
}
__global__ void __launch_bounds__(256)
k_sign_w(const float* __restrict__ W, __nv_bfloat16* __restrict__ dst) {
    long gid = (long)blockIdx.x * blockDim.x + threadIdx.x;
    long n2 = (long)HPAD * HPAD / 2;
    if (gid >= n2) return;
    int r = (int)(gid / (HPAD / 2));
    int c = (int)(gid % (HPAD / 2)) * 2;
    uint32_t w = 0;
    if (r < HDIM && c < HDIM)
        w = sgn_pair_bf(W[(size_t)r * HDIM + c], W[(size_t)r * HDIM + c + 1]);
    *(uint32_t*)&dst[(size_t)r * HPAD + c] = w;
}

// ===========================================================================
// L1: fp16 HMMA, K=3072, 128x128 tile + flag near-threshold (inline s_W1)
// ===========================================================================
__global__ void __launch_bounds__(256, 2)
gemm_l1(const __half* __restrict__ A, const __half* __restrict__ Bw,
        const float* __restrict__ bias, __nv_bfloat16* __restrict__ stepOut)
{
    __shared__ __align__(16) char As[2][128 * APAD * 2];
    __shared__ __align__(16) char Bs[2][128 * APAD * 2];
    __shared__ double smr[256];

    const int tid  = threadIdx.x;
    const int wid  = tid >> 5;
    const int lane = tid & 31;
    const int wm   = wid >> 2;
    const int wn   = wid & 3;
    const int brow = blockIdx.y * 128;
    const int bcol = blockIdx.x * 128;
    const int NC   = DIN / 32;   // 96

    const int lrow = tid >> 2;
    const int lseg = tid & 3;
    const __half* Abase = A  + (size_t)(brow + lrow) * DIN + lseg * 8;
    const __half* Bbase = Bw + (size_t)(bcol + lrow) * DIN + lseg * 8;
    const size_t step64 = (size_t)64 * DIN;
    const uint32_t RSB = APAD * 2;
    const uint32_t st_off = lrow * RSB + lseg * 16;
    const uint32_t as0 = smem_u32(&As[0][0]);
    const uint32_t bs0 = smem_u32(&Bs[0][0]);
    const uint32_t BUFB = 128 * RSB;

    const int aj = lane & 7, asel = lane >> 3;
    const uint32_t a_off = (uint32_t)((wm * 64 + aj + (asel & 1) * 8) * RSB + (asel >> 1) * 16);
    const uint32_t b_off = (uint32_t)((wn * 32 + aj + (asel >> 1) * 8) * RSB + (asel & 1) * 16);

    float acc[4][4][4];
#pragma unroll
    for (int i = 0; i < 4; i++)
#pragma unroll
        for (int j = 0; j < 4; j++)
#pragma unroll
            for (int q = 0; q < 4; q++) acc[i][j][q] = 0.f;

    {
        uint4 a0 = *(const uint4*)Abase;
        uint4 a1 = *(const uint4*)(Abase + step64);
        uint4 b0 = *(const uint4*)Bbase;
        uint4 b1 = *(const uint4*)(Bbase + step64);
        *(uint4*)(As[0] + st_off) = a0;
        *(uint4*)(As[0] + st_off + 64 * RSB) = a1;
        *(uint4*)(Bs[0] + st_off) = b0;
        *(uint4*)(Bs[0] + st_off + 64 * RSB) = b1;
    }
    __syncthreads();

    for (int it = 0; it < NC; it++) {
        const int buf = it & 1;
        uint4 pa0, pa1, pb0, pb1;
        const bool more = (it + 1 < NC);
        if (more) {
            const __half* An = Abase + (size_t)(it + 1) * 32;
            const __half* Bn = Bbase + (size_t)(it + 1) * 32;
            pa0 = *(const uint4*)An;
            pa1 = *(const uint4*)(An + step64);
            pb0 = *(const uint4*)Bn;
            pb1 = *(const uint4*)(Bn + step64);
        }
        const uint32_t ab = as0 + buf * BUFB;
        const uint32_t bb = bs0 + buf * BUFB;
#pragma unroll
        for (int ks = 0; ks < 2; ks++) {
            uint32_t bfr[2][4];
#pragma unroll
            for (int p = 0; p < 2; p++)
                ldm_x4(bfr[p], bb + b_off + p * 16 * RSB + ks * 32);
#pragma unroll
            for (int mf = 0; mf < 4; mf++) {
                uint32_t afr[4];
                ldm_x4(afr, ab + a_off + mf * 16 * RSB + ks * 32);
#pragma unroll
                for (int nf = 0; nf < 4; nf++)
                    mma_f16(acc[mf][nf], afr,
                            bfr[nf >> 1][(nf & 1) * 2], bfr[nf >> 1][(nf & 1) * 2 + 1]);
            }
        }
        if (more) {
            char* ad = As[buf ^ 1] + st_off;
            char* bd = Bs[buf ^ 1] + st_off;
            *(uint4*)ad = pa0;
            *(uint4*)(ad + 64 * RSB) = pa1;
            *(uint4*)bd = pb0;
            *(uint4*)(bd + 64 * RSB) = pb1;
        }
        __syncthreads();
    }

    const float alpha = scale_from_512(d_partials[0], INV_NW1, smr, tid);
    const float athr  = alpha * TAU;
    double mysum = 0.0;
#pragma unroll
    for (int mf = 0; mf < 4; mf++) {
        const int m0 = brow + wm * 64 + mf * 16 + (lane >> 2);
#pragma unroll
        for (int nf = 0; nf < 4; nf++) {
            const int n = bcol + wn * 32 + nf * 8 + 2 * (lane & 3);
            const bool v0 = (n < HDIM), v1 = (n + 1 < HDIM);
            const float bv0 = v0 ? bias[n] : 0.f;
            const float bv1 = v1 ? bias[n + 1] : 0.f;
            float p00 = fmaf(alpha, acc[mf][nf][0], bv0);
            float p01 = fmaf(alpha, acc[mf][nf][1], bv1);
            float p10 = fmaf(alpha, acc[mf][nf][2], bv0);
            float p11 = fmaf(alpha, acc[mf][nf][3], bv1);
            float h00 = (v0 && p00 > 0.f) ? p00 : 0.f;
            float h01 = (v1 && p01 > 0.f) ? p01 : 0.f;
            float h10 = (v0 && p10 > 0.f) ? p10 : 0.f;
            float h11 = (v1 && p11 > 0.f) ? p11 : 0.f;
            mysum += (double)h00 + (double)h01 + (double)h10 + (double)h11;
            uint32_t s0 = (h00 > 0.f ? 0x3F80u : 0u) | ((h01 > 0.f ? 0x3F80u : 0u) << 16);
            uint32_t s1 = (h10 > 0.f ? 0x3F80u : 0u) | ((h11 > 0.f ? 0x3F80u : 0u) << 16);
            *(uint32_t*)&stepOut[(size_t)m0 * HPAD + n] = s0;
            *(uint32_t*)&stepOut[(size_t)(m0 + 8) * HPAD + n] = s1;
#define FLAGCHK(p, h, mm, nn, vv)                                               \
            if ((vv) && fabsf(p) < athr) {                                      \
                unsigned id = atomicAdd(&d_flagcnt, 1u);                        \
                if (id < CAPN) {                                                \
                    d_rec_mn[id] = ((uint32_t)(mm) << 11) | (uint32_t)(nn);     \
                    d_rec_h[id] = (h);                                          \
                }                                                               \
            }
            FLAGCHK(p00, h00, m0,     n,     v0)
            FLAGCHK(p01, h01, m0,     n + 1, v1)
            FLAGCHK(p10, h10, m0 + 8, n,     v0)
            FLAGCHK(p11, h11, m0 + 8, n + 1, v1)
#undef FLAGCHK
        }
    }

    __syncthreads();
    smr[tid] = mysum;
    __syncthreads();
    for (int o = 128; o > 0; o >>= 1) {
        if (tid < o) smr[tid] += smr[tid + o];
        __syncthreads();
    }
    if (tid == 0)
        d_partials[4][blockIdx.y * gridDim.x + blockIdx.x] = smr[0];
}

// ===========================================================================
// Exact fp32 fixup of flagged L1 outputs (warp per record; inline s_W1)
// ===========================================================================
__global__ void __launch_bounds__(256)
k_fixup(const float* __restrict__ x, const float* __restrict__ b1,
        __nv_bfloat16* __restrict__ stepOut)
{
    __shared__ double sm[256];
    const int tid  = threadIdx.x;
    const int lane = tid & 31;
    const float alpha = scale_from_512(d_partials[0], INV_NW1, sm, tid);
    const unsigned gw = (blockIdx.x * blockDim.x + tid) >> 5;
    const unsigned nw = (gridDim.x * blockDim.x) >> 5;
    unsigned cnt = d_flagcnt;
    if (cnt > CAPN) cnt = CAPN;
    for (unsigned i = gw; i < cnt; i += nw) {
        uint32_t mn = d_rec_mn[i];
        int m = (int)(mn >> 11), n = (int)(mn & 2047u);
        const float* xr = x + (size_t)m * DIN;
        const __half* wr = g_w1h + (size_t)n * DIN;
        float s = 0.f;
        for (int k = lane; k < DIN; k += 32)
            s = fmaf(xr[k], __half2float(wr[k]), s);
#pragma unroll
        for (int o = 16; o > 0; o >>= 1)
            s += __shfl_xor_sync(0xffffffffu, s, o);
        if (lane == 0) {
            float p = fmaf(alpha, s, b1[n]);
            float hn = (p > 0.f) ? p : 0.f;
            ((uint16_t*)stepOut)[(size_t)m * HPAD + n] = (hn > 0.f) ? 0x3F80u : 0u;
            atomicAdd(&d_corr, (double)hn - (double)d_rec_h[i]);
        }
    }
}

// ===========================================================================
// L2-4: bf16 HMMA, K=2016 (trimmed); inline alpha reduction in epilogue
// ===========================================================================
__global__ void __launch_bounds__(256, 2)
gemm_mma(const __nv_bfloat16* __restrict__ A, int lda,
         const __nv_bfloat16* __restrict__ Bw, int ldb,
         const float* __restrict__ bias, int K, int Nvalid,
         __nv_bfloat16* __restrict__ stepOut, float* __restrict__ h4Out,
         int sA, int sW, int slot)
{
    __shared__ __align__(16) char As[2][128 * APAD * 2];
    __shared__ __align__(16) char Bs[2][128 * APAD * 2];
    __shared__ double smr[256];

    const int tid  = threadIdx.x;
    const int wid  = tid >> 5;
    const int lane = tid & 31;
    const int wm   = wid >> 2;
    const int wn   = wid & 3;
    const int brow = blockIdx.y * 128;
    const int bcol = blockIdx.x * 128;
    const int NC   = K >> 5;

    const int lrow = tid >> 2;
    const int lseg = tid & 3;
    const __nv_bfloat16* Abase = A  + (size_t)(brow + lrow) * lda + lseg * 8;
    const __nv_bfloat16* Bbase = Bw + (size_t)(bcol + lrow) * ldb + lseg * 8;
    const size_t Astep64 = (size_t)64 * lda;
    const size_t Bstep64 = (size_t)64 * ldb;
    const uint32_t RSB = APAD * 2;
    const uint32_t st_off = lrow * RSB + lseg * 16;
    const uint32_t as0 = smem_u32(&As[0][0]);
    const uint32_t bs0 = smem_u32(&Bs[0][0]);
    const uint32_t BUFB = 128 * RSB;

    const int aj = lane & 7, asel = lane >> 3;
    const uint32_t a_off = (uint32_t)((wm * 64 + aj + (asel & 1) * 8) * RSB + (asel >> 1) * 16);
    const uint32_t b_off = (uint32_t)((wn * 32 + aj + (asel >> 1) * 8) * RSB + (asel & 1) * 16);

    float acc[4][4][4];
#pragma unroll
    for (int i = 0; i < 4; i++)
#pragma unroll
        for (int j = 0; j < 4; j++)
#pragma unroll
            for (int q = 0; q < 4; q++) acc[i][j][q] = 0.f;

    {
        uint4 a0 = *(const uint4*)Abase;
        uint4 a1 = *(const uint4*)(Abase + Astep64);
        uint4 b0 = *(const uint4*)Bbase;
        uint4 b1 = *(const uint4*)(Bbase + Bstep64);
        *(uint4*)(As[0] + st_off) = a0;
        *(uint4*)(As[0] + st_off + 64 * RSB) = a1;
        *(uint4*)(Bs[0] + st_off) = b0;
        *(uint4*)(Bs[0] + st_off + 64 * RSB) = b1;
    }
    __syncthreads();

    for (int it = 0; it < NC; it++) {
        const int buf = it & 1;
        uint4 pa0, pa1, pb0, pb1;
        const bool more = (it + 1 < NC);
        if (more) {
            const __nv_bfloat16* An = Abase + (size_t)(it + 1) * 32;
            const __nv_bfloat16* Bn = Bbase + (size_t)(it + 1) * 32;
            pa0 = *(const uint4*)An;
            pa1 = *(const uint4*)(An + Astep64);
            pb0 = *(const uint4*)Bn;
            pb1 = *(const uint4*)(Bn + Bstep64);
        }
        const uint32_t ab = as0 + buf * BUFB;
        const uint32_t bb = bs0 + buf * BUFB;
#pragma unroll
        for (int ks = 0; ks < 2; ks++) {
            uint32_t bfr[2][4];
#pragma unroll
            for (int p = 0; p < 2; p++)
                ldm_x4(bfr[p], bb + b_off + p * 16 * RSB + ks * 32);
#pragma unroll
            for (int mf = 0; mf < 4; mf++) {
                uint32_t afr[4];
                ldm_x4(afr, ab + a_off + mf * 16 * RSB + ks * 32);
#pragma unroll
                for (int nf = 0; nf < 4; nf++)
                    mma_bf16(acc[mf][nf], afr,
                             bfr[nf >> 1][(nf & 1) * 2], bfr[nf >> 1][(nf & 1) * 2 + 1]);
            }
        }
        if (more) {
            char* ad = As[buf ^ 1] + st_off;
            char* bd = Bs[buf ^ 1] + st_off;
            *(uint4*)ad = pa0;
            *(uint4*)(ad + 64 * RSB) = pa1;
            *(uint4*)bd = pb0;
            *(uint4*)(bd + 64 * RSB) = pb1;
        }
        __syncthreads();
    }

    const float sWsc = scale_from_512(d_partials[sW], INV_NW, smr, tid);
    const float sAsc = scale_from_1024(d_partials[sA], INV_H,
                                       (sA == 4) ? d_corr : 0.0, smr, tid);
    const float alpha = sWsc * sAsc;
    double mysum = 0.0;
#pragma unroll
    for (int mf = 0; mf < 4; mf++) {
        const int m0 = brow + wm * 64 + mf * 16 + (lane >> 2);
#pragma unroll
        for (int nf = 0; nf < 4; nf++) {
            const int n = bcol + wn * 32 + nf * 8 + 2 * (lane & 3);
            const bool v0 = (n < Nvalid), v1 = (n + 1 < Nvalid);
            const float bv0 = v0 ? bias[n] : 0.f;
            const float bv1 = v1 ? bias[n + 1] : 0.f;
            float p00 = fmaf(alpha, acc[mf][nf][0], bv0);
            float p01 = fmaf(alpha, acc[mf][nf][1], bv1);
            float p10 = fmaf(alpha, acc[mf][nf][2], bv0);
            float p11 = fmaf(alpha, acc[mf][nf][3], bv1);
            float h00 = (v0 && p00 > 0.f) ? p00 : 0.f;
            float h01 = (v1 && p01 > 0.f) ? p01 : 0.f;
            float h10 = (v0 && p10 > 0.f) ? p10 : 0.f;
            float h11 = (v1 && p11 > 0.f) ? p11 : 0.f;
            mysum += (double)h00 + (double)h01 + (double)h10 + (double)h11;
            if (stepOut) {
                uint32_t s0 = (h00 > 0.f ? 0x3F80u : 0u) | ((h01 > 0.f ? 0x3F80u : 0u) << 16);
                uint32_t s1 = (h10 > 0.f ? 0x3F80u : 0u) | ((h11 > 0.f ? 0x3F80u : 0u) << 16);
                *(uint32_t*)&stepOut[(size_t)m0 * HPAD + n] = s0;
                *(uint32_t*)&stepOut[(size_t)(m0 + 8) * HPAD + n] = s1;
            }
            if (h4Out && v0) {
                *(float2*)&h4Out[(size_t)m0 * HDIM + n] = make_float2(h00, h01);
                *(float2*)&h4Out[(size_t)(m0 + 8) * HDIM + n] = make_float2(h10, h11);
            }
        }
    }
    __syncthreads();
    smr[tid] = mysum;
    __syncthreads();
    for (int o = 128; o > 0; o >>= 1) {
        if (tid < o) smr[tid] += smr[tid + o];
        __syncthreads();
    }
    if (tid == 0 && slot >= 0)
        d_partials[slot][blockIdx.y * gridDim.x + blockIdx.x] = smr[0];
}

// ===========================================================================
// Final fp32 layer (N=10)
// ===========================================================================
__global__ void __launch_bounds__(256)
fc_out(const float* __restrict__ H4, const float* __restrict__ W5,
       const float* __restrict__ b5, float* __restrict__ out)
{
    int warp = (blockIdx.x * blockDim.x + threadIdx.x) >> 5;
    int lane = threadIdx.x & 31;
    if (warp >= B_ROWS) return;
    const float* h = H4 + (long)warp * HDIM;
    float acc[10];
#pragma unroll
    for (int j = 0; j < 10; j++) acc[j] = 0.f;
    for (int k = lane; k < HDIM; k += 32) {
        float hv = h[k];
#pragma unroll
        for (int j = 0; j < 10; j++)
            acc[j] = fmaf(hv, W5[j * HDIM + k], acc[j]);
    }
#pragma unroll
    for (int j = 0; j < 10; j++)
#pragma unroll
        for (int o = 16; o > 0; o >>= 1)
            acc[j] += __shfl_down_sync(0xffffffffu, acc[j], o);
    if (lane == 0)
#pragma unroll
        for (int j = 0; j < 10; j++)
            out[(long)warp * 10 + j] = acc[j] + b5[j];
}

// ===========================================================================
extern "C" void kernel_launch(void* const* d_in, const int* in_sizes, int n_in,
                              void* d_out, int out_size)
{
    const float* x  = (const float*)d_in[0];
    const float* W1 = (const float*)d_in[1];
    const float* b1 = (const float*)d_in[2];
    const float* W2 = (const float*)d_in[3];
    const float* b2 = (const float*)d_in[4];
    const float* W3 = (const float*)d_in[5];
    const float* b3 = (const float*)d_in[6];
    const float* W4 = (const float*)d_in[7];
    const float* b4 = (const float*)d_in[8];
    const float* W5 = (const float*)d_in[9];
    const float* b5 = (const float*)d_in[10];
    float* out = (float*)d_out;

    __half *xh, *w1h;
    __nv_bfloat16 *sw2, *sw3, *sw4, *stA, *stB;
    float* h4;
    cudaGetSymbolAddress((void**)&xh,  g_xh);
    cudaGetSymbolAddress((void**)&w1h, g_w1h);
    cudaGetSymbolAddress((void**)&sw2, g_sw2);
    cudaGetSymbolAddress((void**)&sw3, g_sw3);
    cudaGetSymbolAddress((void**)&sw4, g_sw4);
    cudaGetSymbolAddress((void**)&stA, g_stepA);
    cudaGetSymbolAddress((void**)&stB, g_stepB);
    cudaGetSymbolAddress((void**)&h4,  g_h4);

    const long nW1 = (long)HDIM * DIN;
    const long nW  = (long)HDIM * HDIM;

    dim3 grid(HPAD / 128, B_ROWS / 128);   // (16, 64) = 1024 CTAs

    reduce_abs_partial<<<RED_BLOCKS, RED_THREADS>>>(W1, nW1, 0);           // 1
    k_cvt_x<<<(int)(((long)B_ROWS * DIN / 8 + 255) / 256), 256>>>(x);      // 2
    k_sign_w1h<<<(int)(((long)HPAD * DIN / 2 + 255) / 256), 256>>>(W1);    // 3
    k_init<<<1, 1>>>();                                                    // 4
    gemm_l1<<<grid, 256>>>(xh, w1h, b1, stA);                              // 5
    k_fixup<<<512, 256>>>(x, b1, stA);                                     // 6

    reduce_abs_partial<<<RED_BLOCKS, RED_THREADS>>>(W2, nW, 1);
    reduce_abs_partial<<<RED_BLOCKS, RED_THREADS>>>(W3, nW, 2);
    reduce_abs_partial<<<RED_BLOCKS, RED_THREADS>>>(W4, nW, 3);
    k_sign_w<<<(int)(((long)HPAD * HPAD / 2 + 255) / 256), 256>>>(W2, sw2);
    k_sign_w<<<(int)(((long)HPAD * HPAD / 2 + 255) / 256), 256>>>(W3, sw3);
    k_sign_w<<<(int)(((long)HPAD * HPAD / 2 + 255) / 256), 256>>>(W4, sw4);

    gemm_mma<<<grid, 256>>>(stA, HPAD, sw2, HPAD, b2, KTRIM, HDIM,
                            stB, nullptr, 4, 1, 5);
    gemm_mma<<<grid, 256>>>(stB, HPAD, sw3, HPAD, b3, KTRIM, HDIM,
                            stA, nullptr, 5, 2, 6);
    gemm_mma<<<grid, 256>>>(stA, HPAD, sw4, HPAD, b4, KTRIM, HDIM,
                            nullptr, h4, 6, 3, -1);

    fc_out<<<(B_ROWS * 32) / 256, 256>>>(h4, W5, b5, out);

    (void)in_sizes; (void)n_in; (void)out_size;
}

// round 17
// speedup vs baseline: 1.0068x; 1.0068x over previous
#include <cuda_runtime.h>
#include <cuda_bf16.h>
#include <cuda_fp16.h>
#include <cstdint>
#include <math.h>

// ===========================================================================
// Net_6983616823390 — binarized MLP (sm_103)
//  L1 : fp16 HMMA K=3072 (single limb) + exact fp32 fixup of |pre|<α·TAU
//  L2-4: bf16 HMMA {0,1}x{-1,0,+1} exact, K=2016 (bit-exact trim)
//  L5 : fp32 SIMT
//  == round-15 base (1404us); change: k_init folded into k_cvt_x ==
// ===========================================================================

#define B_ROWS 8192
#define HDIM   2000
#define HPAD   2048
#define DIN    3072
#define KTRIM  2016

#define RED_BLOCKS 512
#define RED_THREADS 256
#define GPARTS 1024
#define APAD 40
#define CAPN (1u << 21)
#define TAU  0.05f

__device__ float  d_scales[8];
__device__ double d_partials[8][GPARTS];
__device__ double d_corr;
__device__ unsigned d_flagcnt;
__device__ uint32_t d_rec_mn[CAPN];
__device__ float    d_rec_h[CAPN];

__device__ __align__(16) __half g_xh [(size_t)B_ROWS * DIN];
__device__ __align__(16) __half g_w1h[(size_t)HPAD * DIN];
__device__ __align__(16) __nv_bfloat16 g_sw2[(size_t)HPAD * HPAD];
__device__ __align__(16) __nv_bfloat16 g_sw3[(size_t)HPAD * HPAD];
__device__ __align__(16) __nv_bfloat16 g_sw4[(size_t)HPAD * HPAD];
__device__ __align__(16) __nv_bfloat16 g_stepA[(size_t)B_ROWS * HPAD];
__device__ __align__(16) __nv_bfloat16 g_stepB[(size_t)B_ROWS * HPAD];
__device__ __align__(16) float g_h4[(size_t)B_ROWS * HDIM];

__device__ __forceinline__ uint32_t smem_u32(const void* p) {
    uint32_t a;
    asm("{ .reg .u64 t; cvta.to.shared.u64 t, %1; cvt.u32.u64 %0, t; }" : "=r"(a) : "l"(p));
    return a;
}
__device__ __forceinline__ void ldm_x4(uint32_t* r, uint32_t addr) {
    asm volatile("ldmatrix.sync.aligned.m8n8.x4.shared.b16 {%0,%1,%2,%3}, [%4];"
        : "=r"(r[0]), "=r"(r[1]), "=r"(r[2]), "=r"(r[3]) : "r"(addr));
}
__device__ __forceinline__ void mma_bf16(float* c, const uint32_t* a,
                                         uint32_t b0, uint32_t b1) {
    asm volatile(
        "mma.sync.aligned.m16n8k16.row.col.f32.bf16.bf16.f32 "
        "{%0,%1,%2,%3}, {%4,%5,%6,%7}, {%8,%9}, {%0,%1,%2,%3};"
        : "+f"(c[0]), "+f"(c[1]), "+f"(c[2]), "+f"(c[3])
        : "r"(a[0]), "r"(a[1]), "r"(a[2]), "r"(a[3]), "r"(b0), "r"(b1));
}
__device__ __forceinline__ void mma_f16(float* c, const uint32_t* a,
                                        uint32_t b0, uint32_t b1) {
    asm volatile(
        "mma.sync.aligned.m16n8k16.row.col.f32.f16.f16.f32 "
        "{%0,%1,%2,%3}, {%4,%5,%6,%7}, {%8,%9}, {%0,%1,%2,%3};"
        : "+f"(c[0]), "+f"(c[1]), "+f"(c[2]), "+f"(c[3])
        : "r"(a[0]), "r"(a[1]), "r"(a[2]), "r"(a[3]), "r"(b0), "r"(b1));
}

// ===========================================================================
// Deterministic reductions
// ===========================================================================
__global__ void __launch_bounds__(RED_THREADS)
reduce_abs_partial(const float* __restrict__ src, long n, int slot) {
    double s = 0.0;
    long stride = (long)gridDim.x * blockDim.x;
    for (long i = (long)blockIdx.x * blockDim.x + threadIdx.x; i < n; i += stride)
        s += (double)fabsf(src[i]);
    __shared__ double sm[RED_THREADS];
    sm[threadIdx.x] = s; __syncthreads();
    for (int o = RED_THREADS / 2; o > 0; o >>= 1) {
        if (threadIdx.x < o) sm[threadIdx.x] += sm[threadIdx.x + o];
        __syncthreads();
    }
    if (threadIdx.x == 0) d_partials[slot][blockIdx.x] = sm[0];
}
__global__ void __launch_bounds__(512)
reduce_finalize(int slot, double invn, int nparts, int addcorr) {
    __shared__ double sm[512];
    int t = threadIdx.x;
    double v = (t < nparts) ? d_partials[slot][t] : 0.0;
    if (t + 512 < nparts) v += d_partials[slot][t + 512];
    sm[t] = v; __syncthreads();
    for (int o = 256; o > 0; o >>= 1) {
        if (t < o) sm[t] += sm[t + o];
        __syncthreads();
    }
    if (t == 0) {
        double s = sm[0];
        if (addcorr) s += d_corr;
        d_scales[slot] = (float)(s * invn);
    }
}

// ===========================================================================
// Conversions (k_cvt_x also resets fixup counters: runs before gemm_l1)
// ===========================================================================
__global__ void __launch_bounds__(256)
k_cvt_x(const float* __restrict__ x) {
    long gid = (long)blockIdx.x * blockDim.x + threadIdx.x;
    if (gid == 0) { d_flagcnt = 0u; d_corr = 0.0; }
    long n8 = (long)B_ROWS * DIN / 8;
    if (gid >= n8) return;
    const float4 v0 = *(const float4*)&x[gid * 8];
    const float4 v1 = *(const float4*)&x[gid * 8 + 4];
    __half2 h0 = __floats2half2_rn(v0.x, v0.y);
    __half2 h1 = __floats2half2_rn(v0.z, v0.w);
    __half2 h2 = __floats2half2_rn(v1.x, v1.y);
    __half2 h3 = __floats2half2_rn(v1.z, v1.w);
    uint4 o;
    o.x = *(uint32_t*)&h0; o.y = *(uint32_t*)&h1;
    o.z = *(uint32_t*)&h2; o.w = *(uint32_t*)&h3;
    *(uint4*)&g_xh[gid * 8] = o;
}
__global__ void __launch_bounds__(256)
k_sign_w1h(const float* __restrict__ W1) {
    long gid = (long)blockIdx.x * blockDim.x + threadIdx.x;
    long n2 = (long)HPAD * DIN / 2;
    if (gid >= n2) return;
    int r = (int)(gid / (DIN / 2));
    int c = (int)(gid % (DIN / 2)) * 2;
    uint32_t w = 0;
    if (r < HDIM) {
        float a = W1[(size_t)r * DIN + c], b = W1[(size_t)r * DIN + c + 1];
        uint32_t lo = (a > 0.f) ? 0x3C00u : ((a < 0.f) ? 0xBC00u : 0u);
        uint32_t hi = (b > 0.f) ? 0x3C00u : ((b < 0.f) ? 0xBC00u : 0u);
        w = lo | (hi << 16);
    }
    *(uint32_t*)&g_w1h[(size_t)r * DIN + c] = w;
}
__device__ __forceinline__ uint32_t sgn_pair_bf(float a, float b) {
    uint32_t lo = (a > 0.f) ? 0x3F80u : ((a < 0.f) ? 0xBF80u : 0u);
    uint32_t hi = (b > 0.f) ? 0x3F80u : ((b < 0.f) ? 0xBF80u : 0u);
    return lo | (hi << 16);
}
__global__ void __launch_bounds__(256)
k_sign_w(const float* __restrict__ W, __nv_bfloat16* __restrict__ dst) {
    long gid = (long)blockIdx.x * blockDim.x + threadIdx.x;
    long n2 = (long)HPAD * HPAD / 2;
    if (gid >= n2) return;
    int r = (int)(gid / (HPAD / 2));
    int c = (int)(gid % (HPAD / 2)) * 2;
    uint32_t w = 0;
    if (r < HDIM && c < HDIM)
        w = sgn_pair_bf(W[(size_t)r * HDIM + c], W[(size_t)r * HDIM + c + 1]);
    *(uint32_t*)&dst[(size_t)r * HPAD + c] = w;
}

// ===========================================================================
// L1: fp16 HMMA, K=3072, 128x128 tile + flag near-threshold
// ===========================================================================
__global__ void __launch_bounds__(256, 2)
gemm_l1(const __half* __restrict__ A, const __half* __restrict__ Bw,
        const float* __restrict__ bias, __nv_bfloat16* __restrict__ stepOut)
{
    __shared__ __align__(16) char As[2][128 * APAD * 2];
    __shared__ __align__(16) char Bs[2][128 * APAD * 2];
    __shared__ double smr[256];

    const int tid  = threadIdx.x;
    const int wid  = tid >> 5;
    const int lane = tid & 31;
    const int wm   = wid >> 2;
    const int wn   = wid & 3;
    const int brow = blockIdx.y * 128;
    const int bcol = blockIdx.x * 128;
    const int NC   = DIN / 32;   // 96

    const int lrow = tid >> 2;
    const int lseg = tid & 3;
    const __half* Abase = A  + (size_t)(brow + lrow) * DIN + lseg * 8;
    const __half* Bbase = Bw + (size_t)(bcol + lrow) * DIN + lseg * 8;
    const size_t step64 = (size_t)64 * DIN;
    const uint32_t RSB = APAD * 2;
    const uint32_t st_off = lrow * RSB + lseg * 16;
    const uint32_t as0 = smem_u32(&As[0][0]);
    const uint32_t bs0 = smem_u32(&Bs[0][0]);
    const uint32_t BUFB = 128 * RSB;

    const int aj = lane & 7, asel = lane >> 3;
    const uint32_t a_off = (uint32_t)((wm * 64 + aj + (asel & 1) * 8) * RSB + (asel >> 1) * 16);
    const uint32_t b_off = (uint32_t)((wn * 32 + aj + (asel >> 1) * 8) * RSB + (asel & 1) * 16);

    float acc[4][4][4];
#pragma unroll
    for (int i = 0; i < 4; i++)
#pragma unroll
        for (int j = 0; j < 4; j++)
#pragma unroll
            for (int q = 0; q < 4; q++) acc[i][j][q] = 0.f;

    {
        uint4 a0 = *(const uint4*)Abase;
        uint4 a1 = *(const uint4*)(Abase + step64);
        uint4 b0 = *(const uint4*)Bbase;
        uint4 b1 = *(const uint4*)(Bbase + step64);
        *(uint4*)(As[0] + st_off) = a0;
        *(uint4*)(As[0] + st_off + 64 * RSB) = a1;
        *(uint4*)(Bs[0] + st_off) = b0;
        *(uint4*)(Bs[0] + st_off + 64 * RSB) = b1;
    }
    __syncthreads();

    for (int it = 0; it < NC; it++) {
        const int buf = it & 1;
        uint4 pa0, pa1, pb0, pb1;
        const bool more = (it + 1 < NC);
        if (more) {
            const __half* An = Abase + (size_t)(it + 1) * 32;
            const __half* Bn = Bbase + (size_t)(it + 1) * 32;
            pa0 = *(const uint4*)An;
            pa1 = *(const uint4*)(An + step64);
            pb0 = *(const uint4*)Bn;
            pb1 = *(const uint4*)(Bn + step64);
        }
        const uint32_t ab = as0 + buf * BUFB;
        const uint32_t bb = bs0 + buf * BUFB;
#pragma unroll
        for (int ks = 0; ks < 2; ks++) {
            uint32_t bfr[2][4];
#pragma unroll
            for (int p = 0; p < 2; p++)
                ldm_x4(bfr[p], bb + b_off + p * 16 * RSB + ks * 32);
#pragma unroll
            for (int mf = 0; mf < 4; mf++) {
                uint32_t afr[4];
                ldm_x4(afr, ab + a_off + mf * 16 * RSB + ks * 32);
#pragma unroll
                for (int nf = 0; nf < 4; nf++)
                    mma_f16(acc[mf][nf], afr,
                            bfr[nf >> 1][(nf & 1) * 2], bfr[nf >> 1][(nf & 1) * 2 + 1]);
            }
        }
        if (more) {
            char* ad = As[buf ^ 1] + st_off;
            char* bd = Bs[buf ^ 1] + st_off;
            *(uint4*)ad = pa0;
            *(uint4*)(ad + 64 * RSB) = pa1;
            *(uint4*)bd = pb0;
            *(uint4*)(bd + 64 * RSB) = pb1;
        }
        __syncthreads();
    }

    const float alpha = d_scales[0];
    const float athr  = alpha * TAU;
    double mysum = 0.0;
#pragma unroll
    for (int mf = 0; mf < 4; mf++) {
        const int m0 = brow + wm * 64 + mf * 16 + (lane >> 2);
#pragma unroll
        for (int nf = 0; nf < 4; nf++) {
            const int n = bcol + wn * 32 + nf * 8 + 2 * (lane & 3);
            const bool v0 = (n < HDIM), v1 = (n + 1 < HDIM);
            const float bv0 = v0 ? bias[n] : 0.f;
            const float bv1 = v1 ? bias[n + 1] : 0.f;
            float p00 = fmaf(alpha, acc[mf][nf][0], bv0);
            float p01 = fmaf(alpha, acc[mf][nf][1], bv1);
            float p10 = fmaf(alpha, acc[mf][nf][2], bv0);
            float p11 = fmaf(alpha, acc[mf][nf][3], bv1);
            float h00 = (v0 && p00 > 0.f) ? p00 : 0.f;
            float h01 = (v1 && p01 > 0.f) ? p01 : 0.f;
            float h10 = (v0 && p10 > 0.f) ? p10 : 0.f;
            float h11 = (v1 && p11 > 0.f) ? p11 : 0.f;
            mysum += (double)h00 + (double)h01 + (double)h10 + (double)h11;
            uint32_t s0 = (h00 > 0.f ? 0x3F80u : 0u) | ((h01 > 0.f ? 0x3F80u : 0u) << 16);
            uint32_t s1 = (h10 > 0.f ? 0x3F80u : 0u) | ((h11 > 0.f ? 0x3F80u : 0u) << 16);
            *(uint32_t*)&stepOut[(size_t)m0 * HPAD + n] = s0;
            *(uint32_t*)&stepOut[(size_t)(m0 + 8) * HPAD + n] = s1;
#define FLAGCHK(p, h, mm, nn, vv)                                               \
            if ((vv) && fabsf(p) < athr) {                                      \
                unsigned id = atomicAdd(&d_flagcnt, 1u);                        \
                if (id < CAPN) {                                                \
                    d_rec_mn[id] = ((uint32_t)(mm) << 11) | (uint32_t)(nn);     \
                    d_rec_h[id] = (h);                                          \
                }                                                               \
            }
            FLAGCHK(p00, h00, m0,     n,     v0)
            FLAGCHK(p01, h01, m0,     n + 1, v1)
            FLAGCHK(p10, h10, m0 + 8, n,     v0)
            FLAGCHK(p11, h11, m0 + 8, n + 1, v1)
#undef FLAGCHK
        }
    }

    smr[tid] = mysum;
    __syncthreads();
    for (int o = 128; o > 0; o >>= 1) {
        if (tid < o) smr[tid] += smr[tid + o];
        __syncthreads();
    }
    if (tid == 0)
        d_partials[4][blockIdx.y * gridDim.x + blockIdx.x] = smr[0];
}

// ===========================================================================
// Exact fp32 fixup of flagged L1 outputs (warp per record)
// ===========================================================================
__global__ void __launch_bounds__(256)
k_fixup(const float* __restrict__ x, const float* __restrict__ b1,
        __nv_bfloat16* __restrict__ stepOut)
{
    const int lane = threadIdx.x & 31;
    const unsigned gw = (blockIdx.x * blockDim.x + threadIdx.x) >> 5;
    const unsigned nw = (gridDim.x * blockDim.x) >> 5;
    unsigned cnt = d_flagcnt;
    if (cnt > CAPN) cnt = CAPN;
    const float alpha = d_scales[0];
    for (unsigned i = gw; i < cnt; i += nw) {
        uint32_t mn = d_rec_mn[i];
        int m = (int)(mn >> 11), n = (int)(mn & 2047u);
        const float* xr = x + (size_t)m * DIN;
        const __half* wr = g_w1h + (size_t)n * DIN;
        float s = 0.f;
        for (int k = lane; k < DIN; k += 32)
            s = fmaf(xr[k], __half2float(wr[k]), s);
#pragma unroll
        for (int o = 16; o > 0; o >>= 1)
            s += __shfl_xor_sync(0xffffffffu, s, o);
        if (lane == 0) {
            float p = fmaf(alpha, s, b1[n]);
            float hn = (p > 0.f) ? p : 0.f;
            ((uint16_t*)stepOut)[(size_t)m * HPAD + n] = (hn > 0.f) ? 0x3F80u : 0u;
            atomicAdd(&d_corr, (double)hn - (double)d_rec_h[i]);
        }
    }
}

// ===========================================================================
// L2-4: bf16 HMMA, K=2016 (trimmed, bit-exact)
// ===========================================================================
__global__ void __launch_bounds__(256, 2)
gemm_mma(const __nv_bfloat16* __restrict__ A, int lda,
         const __nv_bfloat16* __restrict__ Bw, int ldb,
         const float* __restrict__ bias, int K, int Nvalid,
         __nv_bfloat16* __restrict__ stepOut, float* __restrict__ h4Out,
         int sA, int sW, int slot)
{
    __shared__ __align__(16) char As[2][128 * APAD * 2];
    __shared__ __align__(16) char Bs[2][128 * APAD * 2];
    __shared__ double smr[256];

    const int tid  = threadIdx.x;
    const int wid  = tid >> 5;
    const int lane = tid & 31;
    const int wm   = wid >> 2;
    const int wn   = wid & 3;
    const int brow = blockIdx.y * 128;
    const int bcol = blockIdx.x * 128;
    const int NC   = K >> 5;

    const int lrow = tid >> 2;
    const int lseg = tid & 3;
    const __nv_bfloat16* Abase = A  + (size_t)(brow + lrow) * lda + lseg * 8;
    const __nv_bfloat16* Bbase = Bw + (size_t)(bcol + lrow) * ldb + lseg * 8;
    const size_t Astep64 = (size_t)64 * lda;
    const size_t Bstep64 = (size_t)64 * ldb;
    const uint32_t RSB = APAD * 2;
    const uint32_t st_off = lrow * RSB + lseg * 16;
    const uint32_t as0 = smem_u32(&As[0][0]);
    const uint32_t bs0 = smem_u32(&Bs[0][0]);
    const uint32_t BUFB = 128 * RSB;

    const int aj = lane & 7, asel = lane >> 3;
    const uint32_t a_off = (uint32_t)((wm * 64 + aj + (asel & 1) * 8) * RSB + (asel >> 1) * 16);
    const uint32_t b_off = (uint32_t)((wn * 32 + aj + (asel >> 1) * 8) * RSB + (asel & 1) * 16);

    float acc[4][4][4];
#pragma unroll
    for (int i = 0; i < 4; i++)
#pragma unroll
        for (int j = 0; j < 4; j++)
#pragma unroll
            for (int q = 0; q < 4; q++) acc[i][j][q] = 0.f;

    {
        uint4 a0 = *(const uint4*)Abase;
        uint4 a1 = *(const uint4*)(Abase + Astep64);
        uint4 b0 = *(const uint4*)Bbase;
        uint4 b1 = *(const uint4*)(Bbase + Bstep64);
        *(uint4*)(As[0] + st_off) = a0;
        *(uint4*)(As[0] + st_off + 64 * RSB) = a1;
        *(uint4*)(Bs[0] + st_off) = b0;
        *(uint4*)(Bs[0] + st_off + 64 * RSB) = b1;
    }
    __syncthreads();

    for (int it = 0; it < NC; it++) {
        const int buf = it & 1;
        uint4 pa0, pa1, pb0, pb1;
        const bool more = (it + 1 < NC);
        if (more) {
            const __nv_bfloat16* An = Abase + (size_t)(it + 1) * 32;
            const __nv_bfloat16* Bn = Bbase + (size_t)(it + 1) * 32;
            pa0 = *(const uint4*)An;
            pa1 = *(const uint4*)(An + Astep64);
            pb0 = *(const uint4*)Bn;
            pb1 = *(const uint4*)(Bn + Bstep64);
        }
        const uint32_t ab = as0 + buf * BUFB;
        const uint32_t bb = bs0 + buf * BUFB;
#pragma unroll
        for (int ks = 0; ks < 2; ks++) {
            uint32_t bfr[2][4];
#pragma unroll
            for (int p = 0; p < 2; p++)
                ldm_x4(bfr[p], bb + b_off + p * 16 * RSB + ks * 32);
#pragma unroll
            for (int mf = 0; mf < 4; mf++) {
                uint32_t afr[4];
                ldm_x4(afr, ab + a_off + mf * 16 * RSB + ks * 32);
#pragma unroll
                for (int nf = 0; nf < 4; nf++)
                    mma_bf16(acc[mf][nf], afr,
                             bfr[nf >> 1][(nf & 1) * 2], bfr[nf >> 1][(nf & 1) * 2 + 1]);
            }
        }
        if (more) {
            char* ad = As[buf ^ 1] + st_off;
            char* bd = Bs[buf ^ 1] + st_off;
            *(uint4*)ad = pa0;
            *(uint4*)(ad + 64 * RSB) = pa1;
            *(uint4*)bd = pb0;
            *(uint4*)(bd + 64 * RSB) = pb1;
        }
        __syncthreads();
    }

    const float alpha = d_scales[sW] * d_scales[sA];
    double mysum = 0.0;
#pragma unroll
    for (int mf = 0; mf < 4; mf++) {
        const int m0 = brow + wm * 64 + mf * 16 + (lane >> 2);
#pragma unroll
        for (int nf = 0; nf < 4; nf++) {
            const int n = bcol + wn * 32 + nf * 8 + 2 * (lane & 3);
            const bool v0 = (n < Nvalid), v1 = (n + 1 < Nvalid);
            const float bv0 = v0 ? bias[n] : 0.f;
            const float bv1 = v1 ? bias[n + 1] : 0.f;
            float p00 = fmaf(alpha, acc[mf][nf][0], bv0);
            float p01 = fmaf(alpha, acc[mf][nf][1], bv1);
            float p10 = fmaf(alpha, acc[mf][nf][2], bv0);
            float p11 = fmaf(alpha, acc[mf][nf][3], bv1);
            float h00 = (v0 && p00 > 0.f) ? p00 : 0.f;
            float h01 = (v1 && p01 > 0.f) ? p01 : 0.f;
            float h10 = (v0 && p10 > 0.f) ? p10 : 0.f;
            float h11 = (v1 && p11 > 0.f) ? p11 : 0.f;
            mysum += (double)h00 + (double)h01 + (double)h10 + (double)h11;
            if (stepOut) {
                uint32_t s0 = (h00 > 0.f ? 0x3F80u : 0u) | ((h01 > 0.f ? 0x3F80u : 0u) << 16);
                uint32_t s1 = (h10 > 0.f ? 0x3F80u : 0u) | ((h11 > 0.f ? 0x3F80u : 0u) << 16);
                *(uint32_t*)&stepOut[(size_t)m0 * HPAD + n] = s0;
                *(uint32_t*)&stepOut[(size_t)(m0 + 8) * HPAD + n] = s1;
            }
            if (h4Out && v0) {
                *(float2*)&h4Out[(size_t)m0 * HDIM + n] = make_float2(h00, h01);
                *(float2*)&h4Out[(size_t)(m0 + 8) * HDIM + n] = make_float2(h10, h11);
            }
        }
    }
    smr[tid] = mysum;
    __syncthreads();
    for (int o = 128; o > 0; o >>= 1) {
        if (tid < o) smr[tid] += smr[tid + o];
        __syncthreads();
    }
    if (tid == 0 && slot >= 0)
        d_partials[slot][blockIdx.y * gridDim.x + blockIdx.x] = smr[0];
}

// ===========================================================================
// Final fp32 layer (N=10)
// ===========================================================================
__global__ void __launch_bounds__(256)
fc_out(const float* __restrict__ H4, const float* __restrict__ W5,
       const float* __restrict__ b5, float* __restrict__ out)
{
    int warp = (blockIdx.x * blockDim.x + threadIdx.x) >> 5;
    int lane = threadIdx.x & 31;
    if (warp >= B_ROWS) return;
    const float* h = H4 + (long)warp * HDIM;
    float acc[10];
#pragma unroll
    for (int j = 0; j < 10; j++) acc[j] = 0.f;
    for (int k = lane; k < HDIM; k += 32) {
        float hv = h[k];
#pragma unroll
        for (int j = 0; j < 10; j++)
            acc[j] = fmaf(hv, W5[j * HDIM + k], acc[j]);
    }
#pragma unroll
    for (int j = 0; j < 10; j++)
#pragma unroll
        for (int o = 16; o > 0; o >>= 1)
            acc[j] += __shfl_down_sync(0xffffffffu, acc[j], o);
    if (lane == 0)
#pragma unroll
        for (int j = 0; j < 10; j++)
            out[(long)warp * 10 + j] = acc[j] + b5[j];
}

// ===========================================================================
extern "C" void kernel_launch(void* const* d_in, const int* in_sizes, int n_in,
                              void* d_out, int out_size)
{
    const float* x  = (const float*)d_in[0];
    const float* W1 = (const float*)d_in[1];
    const float* b1 = (const float*)d_in[2];
    const float* W2 = (const float*)d_in[3];
    const float* b2 = (const float*)d_in[4];
    const float* W3 = (const float*)d_in[5];
    const float* b3 = (const float*)d_in[6];
    const float* W4 = (const float*)d_in[7];
    const float* b4 = (const float*)d_in[8];
    const float* W5 = (const float*)d_in[9];
    const float* b5 = (const float*)d_in[10];
    float* out = (float*)d_out;

    __half *xh, *w1h;
    __nv_bfloat16 *sw2, *sw3, *sw4, *stA, *stB;
    float* h4;
    cudaGetSymbolAddress((void**)&xh,  g_xh);
    cudaGetSymbolAddress((void**)&w1h, g_w1h);
    cudaGetSymbolAddress((void**)&sw2, g_sw2);
    cudaGetSymbolAddress((void**)&sw3, g_sw3);
    cudaGetSymbolAddress((void**)&sw4, g_sw4);
    cudaGetSymbolAddress((void**)&stA, g_stepA);
    cudaGetSymbolAddress((void**)&stB, g_stepB);
    cudaGetSymbolAddress((void**)&h4,  g_h4);

    const long nW1 = (long)HDIM * DIN;
    const long nW  = (long)HDIM * HDIM;
    const double invH = 1.0 / ((double)B_ROWS * HDIM);

    dim3 grid(HPAD / 128, B_ROWS / 128);   // (16, 64) = 1024 CTAs

    reduce_abs_partial<<<RED_BLOCKS, RED_THREADS>>>(W1, nW1, 0);           // 1
    reduce_finalize<<<1, 512>>>(0, 1.0 / (double)nW1, RED_BLOCKS, 0);      // 2
    k_cvt_x<<<(int)(((long)B_ROWS * DIN / 8 + 255) / 256), 256>>>(x);      // 3 (+reset)
    k_sign_w1h<<<(int)(((long)HPAD * DIN / 2 + 255) / 256), 256>>>(W1);    // 4
    gemm_l1<<<grid, 256>>>(xh, w1h, b1, stA);                              // 5
    k_fixup<<<512, 256>>>(x, b1, stA);                                     // 6
    reduce_finalize<<<1, 512>>>(4, invH, GPARTS, 1);                       // 7

    reduce_abs_partial<<<RED_BLOCKS, RED_THREADS>>>(W2, nW, 1);
    reduce_finalize<<<1, 512>>>(1, 1.0 / (double)nW, RED_BLOCKS, 0);
    reduce_abs_partial<<<RED_BLOCKS, RED_THREADS>>>(W3, nW, 2);
    reduce_finalize<<<1, 512>>>(2, 1.0 / (double)nW, RED_BLOCKS, 0);
    reduce_abs_partial<<<RED_BLOCKS, RED_THREADS>>>(W4, nW, 3);
    reduce_finalize<<<1, 512>>>(3, 1.0 / (double)nW, RED_BLOCKS, 0);
    k_sign_w<<<(int)(((long)HPAD * HPAD / 2 + 255) / 256), 256>>>(W2, sw2);
    k_sign_w<<<(int)(((long)HPAD * HPAD / 2 + 255) / 256), 256>>>(W3, sw3);
    k_sign_w<<<(int)(((long)HPAD * HPAD / 2 + 255) / 256), 256>>>(W4, sw4);

    gemm_mma<<<grid, 256>>>(stA, HPAD, sw2, HPAD, b2, KTRIM, HDIM,
                            stB, nullptr, 4, 1, 5);
    reduce_finalize<<<1, 512>>>(5, invH, GPARTS, 0);
    gemm_mma<<<grid, 256>>>(stB, HPAD, sw3, HPAD, b3, KTRIM, HDIM,
                            stA, nullptr, 5, 2, 6);
    reduce_finalize<<<1, 512>>>(6, invH, GPARTS, 0);
    gemm_mma<<<grid, 256>>>(stA, HPAD, sw4, HPAD, b4, KTRIM, HDIM,
                            nullptr, h4, 6, 3, -1);

    fc_out<<<(B_ROWS * 32) / 256, 256>>>(h4, W5, b5, out);

    (void)in_sizes; (void)n_in; (void)out_size;
}